// round 13
// baseline (speedup 1.0000x reference)
#include <cuda_runtime.h>
#include <cuda_fp16.h>
#include <cstdint>

#define L_SEQ   2048
#define D_HEAD  64
#define N_HEADS 8
#define N_BH    16
#define D_IN    512
#define QTILE   128
#define KTILE   128
#define NKB2    (L_SEQ / KTILE)     // 16 k-chunks per row group

// Static device scratch (no allocs allowed)
__device__ __half g_q16[N_BH * L_SEQ * D_HEAD];          // 4 MB, qh/8 in fp16
__device__ __half g_k16[N_BH * L_SEQ * D_HEAD];          // 4 MB, kh in fp16
__device__ __half g_w16hi[2 * 512 * D_IN];               // 1 MB, W hi fp16
__device__ __half g_w16lo[2 * 512 * D_IN];               // 1 MB, W lo fp16
__device__ float  g_part[N_BH * L_SEQ * NKB2];           // 2 MB partial row sums
__device__ int    g_cnt[N_BH * (L_SEQ / QTILE)];         // 256 group counters

// ---------------------------------------------------------------------------
__device__ __forceinline__ float exp2_fast(float t)
{
    const float MAGIC = 12582912.0f;
    float z = t + MAGIC;
    float n = z - MAGIC;
    float f = t - n;
    float p = 0.00015403530393381609f;
    p = fmaf(p, f, 0.0013333558146428443f);
    p = fmaf(p, f, 0.009618129107628477f);
    p = fmaf(p, f, 0.05550410866482158f);
    p = fmaf(p, f, 0.24022650695910072f);
    p = fmaf(p, f, 0.6931471805599453f);
    p = fmaf(p, f, 1.0f);
    return __int_as_float(__float_as_int(p) + (((int)n) << 23));
}

__device__ __forceinline__ void mma_f16(float* c,
    uint32_t a0, uint32_t a1, uint32_t a2, uint32_t a3,
    uint32_t b0, uint32_t b1)
{
    asm volatile(
        "mma.sync.aligned.m16n8k16.row.col.f32.f16.f16.f32 "
        "{%0,%1,%2,%3}, {%4,%5,%6,%7}, {%8,%9}, {%0,%1,%2,%3};"
        : "+f"(c[0]), "+f"(c[1]), "+f"(c[2]), "+f"(c[3])
        : "r"(a0), "r"(a1), "r"(a2), "r"(a3), "r"(b0), "r"(b1));
}

__device__ __forceinline__ void ldsm4(uint32_t& r0, uint32_t& r1,
                                      uint32_t& r2, uint32_t& r3, uint32_t a)
{
    asm volatile("ldmatrix.sync.aligned.m8n8.x4.shared.b16 {%0,%1,%2,%3}, [%4];"
                 : "=r"(r0), "=r"(r1), "=r"(r2), "=r"(r3) : "r"(a));
}

__device__ __forceinline__ uint32_t smem_u32(const void* p) {
    uint32_t a;
    asm("{ .reg .u64 t; cvta.to.shared.u64 t, %1; cvt.u32.u64 %0, t; }" : "=r"(a) : "l"(p));
    return a;
}

// pack 8 fp32 -> 8 fp16 (hi) and 8 fp16 (lo residual)
__device__ __forceinline__ void split8(const float* x, uint4& hi, uint4& lo)
{
    __half2 h[4], l[4];
    #pragma unroll
    for (int i = 0; i < 4; i++) {
        float v0 = x[2*i], v1 = x[2*i+1];
        __half h0 = __float2half_rn(v0);
        __half h1 = __float2half_rn(v1);
        __half l0 = __float2half_rn(v0 - __half2float(h0));
        __half l1 = __float2half_rn(v1 - __half2float(h1));
        h[i] = __halves2half2(h0, h1);
        l[i] = __halves2half2(l0, l1);
    }
    hi = *(uint4*)h;
    lo = *(uint4*)l;
}

// ---------------------------------------------------------------------------
// Pre-convert Wq/Wk to fp16 hi/lo (once, instead of per-CTA in proj).
// Also resets the score-group counters.
// ---------------------------------------------------------------------------
__global__ __launch_bounds__(256) void wcvt_kernel(
    const float* __restrict__ Wq, const float* __restrict__ Wk)
{
    const int z = blockIdx.y;
    const float* W = z ? Wk : Wq;
    int i = blockIdx.x * 256 + threadIdx.x;        // 0..32767, 8 elems each
    float v[8];
    *(float4*)&v[0] = *(const float4*)&W[i*8];
    *(float4*)&v[4] = *(const float4*)&W[i*8 + 4];
    uint4 hi, lo;
    split8(v, hi, lo);
    *(uint4*)&g_w16hi[(size_t)z * 512 * D_IN + i*8] = hi;
    *(uint4*)&g_w16lo[(size_t)z * 512 * D_IN + i*8] = lo;
    if (blockIdx.x == 0 && blockIdx.y == 0)
        g_cnt[threadIdx.x] = 0;
}

// ---------------------------------------------------------------------------
// Projection via fp16 hi/lo split (3 passes: hh + hl + lh) — fp32-accurate.
// W side now reads pre-converted fp16 (no per-CTA split).
// ---------------------------------------------------------------------------
#define PKS 32

__global__ __launch_bounds__(256) void proj_f16_kernel(
    const float* __restrict__ q, const float* __restrict__ k,
    float* __restrict__ qh_out)
{
    __shared__ __align__(16) char sAhi[128 * 64];
    __shared__ __align__(16) char sAlo[128 * 64];
    __shared__ __align__(16) char sBhi[128 * 64];
    __shared__ __align__(16) char sBlo[128 * 64];

    const int tid = threadIdx.x;
    const int z = blockIdx.z;
    const float* X = z ? k : q;
    const __half* Whi = g_w16hi + (size_t)z * 512 * D_IN;
    const __half* Wlo = g_w16lo + (size_t)z * 512 * D_IN;

    const int w    = tid >> 5;
    const int lane = tid & 31;
    const int g    = lane >> 2;
    const int t    = lane & 3;
    const int wr   = w & 3;
    const int wc   = w >> 2;
    const int n0   = blockIdx.y * 128;
    const int o0   = blockIdx.x * 128;

    const uint32_t sAhiB = smem_u32(sAhi), sAloB = smem_u32(sAlo);
    const uint32_t sBhiB = smem_u32(sBhi), sBloB = smem_u32(sBlo);

    float c[2][8][4];
    #pragma unroll
    for (int mt = 0; mt < 2; mt++)
        #pragma unroll
        for (int j = 0; j < 8; j++)
            #pragma unroll
            for (int q2 = 0; q2 < 4; q2++) c[mt][j][q2] = 0.f;

    const int R0 = wr * 32;
    const int C0 = wc * 64;

    const int aHalf = lane >> 4;
    uint32_t aRow[2]; int aXor[2];
    #pragma unroll
    for (int mt = 0; mt < 2; mt++) {
        int row = R0 + mt*16 + (lane & 15);
        aRow[mt] = row * 64;
        aXor[mt] = (row >> 1) & 3;
    }
    const int qd = lane >> 3;
    const int bHalf = qd & 1;
    uint32_t bRow[4]; int bXor[4];
    #pragma unroll
    for (int jp = 0; jp < 4; jp++) {
        int row = C0 + (jp*2 + (qd >> 1)) * 8 + (lane & 7);
        bRow[jp] = row * 64;
        bXor[jp] = (row >> 1) & 3;
    }

    for (int k0 = 0; k0 < D_IN; k0 += PKS) {
        float xv[2][8];
        uint4 whi[2], wlo[2];
        #pragma unroll
        for (int i = 0; i < 2; i++) {
            int idx = tid + 256 * i;
            int r = idx >> 2, ch = idx & 3;
            *(float4*)&xv[i][0] = *(const float4*)&X[(size_t)(n0 + r) * D_IN + k0 + ch*8];
            *(float4*)&xv[i][4] = *(const float4*)&X[(size_t)(n0 + r) * D_IN + k0 + ch*8 + 4];
            whi[i] = *(const uint4*)&Whi[(size_t)(o0 + r) * D_IN + k0 + ch*8];
            wlo[i] = *(const uint4*)&Wlo[(size_t)(o0 + r) * D_IN + k0 + ch*8];
        }
        __syncthreads();
        #pragma unroll
        for (int i = 0; i < 2; i++) {
            int idx = tid + 256 * i;
            int r = idx >> 2, ch = idx & 3;
            int off = r * 64 + (ch ^ ((r >> 1) & 3)) * 16;
            uint4 hi, lo;
            split8(xv[i], hi, lo);
            *(uint4*)(sAhi + off) = hi;
            *(uint4*)(sAlo + off) = lo;
            *(uint4*)(sBhi + off) = whi[i];
            *(uint4*)(sBlo + off) = wlo[i];
        }
        __syncthreads();

        #pragma unroll
        for (int s = 0; s < 2; s++) {
            uint32_t ah[2][4], al[2][4];
            #pragma unroll
            for (int mt = 0; mt < 2; mt++) {
                int chk = ((2*s + aHalf) ^ aXor[mt]) * 16;
                ldsm4(ah[mt][0], ah[mt][1], ah[mt][2], ah[mt][3], sAhiB + aRow[mt] + chk);
                ldsm4(al[mt][0], al[mt][1], al[mt][2], al[mt][3], sAloB + aRow[mt] + chk);
            }
            uint32_t bh[8][2], bl[8][2];
            #pragma unroll
            for (int jp = 0; jp < 4; jp++) {
                int chk = ((2*s + bHalf) ^ bXor[jp]) * 16;
                uint32_t r0, r1, r2, r3;
                ldsm4(r0, r1, r2, r3, sBhiB + bRow[jp] + chk);
                bh[jp*2][0] = r0; bh[jp*2][1] = r1;
                bh[jp*2+1][0] = r2; bh[jp*2+1][1] = r3;
                ldsm4(r0, r1, r2, r3, sBloB + bRow[jp] + chk);
                bl[jp*2][0] = r0; bl[jp*2][1] = r1;
                bl[jp*2+1][0] = r2; bl[jp*2+1][1] = r3;
            }
            #pragma unroll
            for (int mt = 0; mt < 2; mt++)
                #pragma unroll
                for (int j = 0; j < 8; j++) {
                    mma_f16(c[mt][j], ah[mt][0], ah[mt][1], ah[mt][2], ah[mt][3],
                            bh[j][0], bh[j][1]);
                    mma_f16(c[mt][j], ah[mt][0], ah[mt][1], ah[mt][2], ah[mt][3],
                            bl[j][0], bl[j][1]);
                    mma_f16(c[mt][j], al[mt][0], al[mt][1], al[mt][2], al[mt][3],
                            bh[j][0], bh[j][1]);
                }
        }
    }

    const int b  = n0 >> 11;
    const int l0 = n0 & 2047;
    const int h  = (o0 >> 6) + wc;
    const size_t hb = (size_t)(b * N_HEADS + h) * L_SEQ * D_HEAD;
    __half* H = z ? g_k16 : g_q16;
    const float sc = z ? 1.0f : 0.125f;
    #pragma unroll
    for (int mt = 0; mt < 2; mt++) {
        const int r0 = l0 + R0 + mt*16 + g;
        #pragma unroll
        for (int j = 0; j < 8; j++) {
            const int d = j*8 + 2*t;
            if (!z) {
                *(float2*)&qh_out[hb + (size_t)r0       * D_HEAD + d] = make_float2(c[mt][j][0], c[mt][j][1]);
                *(float2*)&qh_out[hb + (size_t)(r0 + 8) * D_HEAD + d] = make_float2(c[mt][j][2], c[mt][j][3]);
            }
            *(__half2*)&H[hb + (size_t)r0       * D_HEAD + d] =
                __floats2half2_rn(c[mt][j][0] * sc, c[mt][j][1] * sc);
            *(__half2*)&H[hb + (size_t)(r0 + 8) * D_HEAD + d] =
                __floats2half2_rn(c[mt][j][2] * sc, c[mt][j][3] * sc);
        }
    }
}

// ---------------------------------------------------------------------------
// fp16 scores, 512 threads / 16 warps (4x4), warp tile 32x32.
// Epilogue: exp -> swizzled smem stage (overlays dead tiles) -> cross-CTA
// softmax -> fully-coalesced float4 streaming writes.
// Dynamic smem: 64 KB (tiles 32 KB during mainloop; 64 KB stage after).
// ---------------------------------------------------------------------------
extern __shared__ char dynS[];

__global__ __launch_bounds__(512, 2) void score_f16_kernel(
    const int* __restrict__ mask, float* __restrict__ attn)
{
    __shared__ float sMaskF[KTILE];
    __shared__ float sRS[4][QTILE];
    __shared__ float sInv[QTILE];

    char* sQraw = dynS;                 // 16 KB
    char* sKraw = dynS + 16384;         // 16 KB
    char* stage = dynS;                 // 64 KB overlay (after mainloop)

    const int tid  = threadIdx.x;
    const int w    = tid >> 5;
    const int lane = tid & 31;
    const int g    = lane >> 2;
    const int t    = lane & 3;
    const int wr   = w & 3;            // row block (32 rows)
    const int wc   = w >> 2;           // col block (32 cols)

    const int kbi = blockIdx.x;
    const int kb  = kbi * KTILE;
    const int qb  = blockIdx.y * QTILE;
    const int bh  = blockIdx.z;
    const int gi  = bh * (L_SEQ / QTILE) + blockIdx.y;

    const uint4* Qg = (const uint4*)(g_q16 + ((size_t)bh * L_SEQ + qb) * D_HEAD);
    const uint4* Kg = (const uint4*)(g_k16 + ((size_t)bh * L_SEQ + kb) * D_HEAD);
    #pragma unroll
    for (int i = 0; i < 2; i++) {
        int idx = tid + 512 * i;
        int r = idx >> 3, ch = idx & 7;
        int chs = ch ^ (r & 7);
        *(uint4*)(sQraw + r * 128 + chs * 16) = Qg[idx];
        *(uint4*)(sKraw + r * 128 + chs * 16) = Kg[idx];
    }
    if (tid < KTILE) sMaskF[tid] = mask[(bh >> 3) * L_SEQ + kb + tid] ? 1.0f : 0.0f;
    __syncthreads();

    const uint32_t sQb = smem_u32(sQraw);
    const uint32_t sKb = smem_u32(sKraw);
    const int R0 = wr * 32;
    const int C0 = wc * 32;

    const int aHalf = lane >> 4;
    uint32_t aBase[2]; int aXor[2];
    #pragma unroll
    for (int mt = 0; mt < 2; mt++) {
        int row = R0 + mt*16 + (lane & 15);
        aBase[mt] = sQb + row * 128;
        aXor[mt]  = row & 7;
    }
    const int qd = lane >> 3;
    const int bHalf = qd & 1;
    uint32_t bBase[2]; int bXor[2];
    #pragma unroll
    for (int jp = 0; jp < 2; jp++) {
        int row = C0 + (jp*2 + (qd >> 1)) * 8 + (lane & 7);
        bBase[jp] = sKb + row * 128;
        bXor[jp]  = row & 7;
    }

    float c[2][4][4];
    #pragma unroll
    for (int mt = 0; mt < 2; mt++)
        #pragma unroll
        for (int j = 0; j < 4; j++)
            #pragma unroll
            for (int q2 = 0; q2 < 4; q2++) c[mt][j][q2] = 0.f;

    #pragma unroll
    for (int s = 0; s < 4; s++) {
        uint32_t a[2][4];
        #pragma unroll
        for (int mt = 0; mt < 2; mt++) {
            int chk = (2*s + aHalf) ^ aXor[mt];
            ldsm4(a[mt][0], a[mt][1], a[mt][2], a[mt][3], aBase[mt] + chk * 16);
        }
        uint32_t b[4][2];
        #pragma unroll
        for (int jp = 0; jp < 2; jp++) {
            int chk = (2*s + bHalf) ^ bXor[jp];
            uint32_t r0, r1, r2, r3;
            ldsm4(r0, r1, r2, r3, bBase[jp] + chk * 16);
            b[jp*2][0] = r0; b[jp*2][1] = r1;
            b[jp*2+1][0] = r2; b[jp*2+1][1] = r3;
        }
        #pragma unroll
        for (int mt = 0; mt < 2; mt++)
            #pragma unroll
            for (int j = 0; j < 4; j++)
                mma_f16(c[mt][j], a[mt][0], a[mt][1], a[mt][2], a[mt][3],
                        b[j][0], b[j][1]);
    }

    __syncthreads();                   // all ldsm done -> tiles dead, stage live

    // exp + mask; write unnormalized exp to swizzled stage; row partial sums
    const float C = 1.4426950408889634f;       // log2(e)
    float rs[4] = {0.f, 0.f, 0.f, 0.f};
    #pragma unroll
    for (int mt = 0; mt < 2; mt++) {
        const int r0a = R0 + mt*16 + g;
        const int r0b = r0a + 8;
        const int swa = (r0a & 7) << 2;        // == swb: +8 keeps (&7)
        #pragma unroll
        for (int j = 0; j < 4; j++) {
            const int col = C0 + j*8 + 2*t;
            const float m0 = sMaskF[col], m1 = sMaskF[col + 1];
            float v0 = exp2_fast(c[mt][j][0] * C) * m0;
            float v1 = exp2_fast(c[mt][j][1] * C) * m1;
            float v2 = exp2_fast(c[mt][j][2] * C) * m0;
            float v3 = exp2_fast(c[mt][j][3] * C) * m1;
            rs[mt*2 + 0] += v0 + v1;
            rs[mt*2 + 1] += v2 + v3;
            const int ch8 = (col >> 1);        // 8B chunk index (col even)
            *(float2*)(stage + r0a * 512 + (ch8 ^ swa) * 8) = make_float2(v0, v1);
            *(float2*)(stage + r0b * 512 + (ch8 ^ swa) * 8) = make_float2(v2, v3);
        }
    }
    #pragma unroll
    for (int off = 1; off <= 2; off <<= 1)
        #pragma unroll
        for (int i = 0; i < 4; i++)
            rs[i] += __shfl_xor_sync(0xffffffffu, rs[i], off);
    if (t == 0) {
        sRS[wc][R0 +  0 + g] = rs[0];
        sRS[wc][R0 +  8 + g] = rs[1];
        sRS[wc][R0 + 16 + g] = rs[2];
        sRS[wc][R0 + 24 + g] = rs[3];
    }
    __syncthreads();

    if (tid < QTILE)
        g_part[((size_t)bh * L_SEQ + qb + tid) * NKB2 + kbi] =
            (sRS[0][tid] + sRS[1][tid]) + (sRS[2][tid] + sRS[3][tid]);
    __syncthreads();

    // Cross-CTA: release, count in, spin for the 16-CTA row group
    if (tid == 0) {
        __threadfence();
        atomicAdd(&g_cnt[gi], 1);
        while (atomicAdd(&g_cnt[gi], 0) < NKB2) __nanosleep(128);
        __threadfence();
    }
    __syncthreads();

    if (tid < QTILE) {
        const float4* p = (const float4*)(g_part + ((size_t)bh * L_SEQ + qb + tid) * NKB2);
        float s = 0.f;
        #pragma unroll
        for (int i = 0; i < NKB2 / 4; i++) {
            float4 v = p[i];
            s += (v.x + v.y) + (v.z + v.w);
        }
        sInv[tid] = 1.0f / s;
    }
    __syncthreads();

    // Fully-coalesced writeout: warp w owns rows w, w+16, ..., w+112
    #pragma unroll
    for (int rr = 0; rr < 8; rr++) {
        const int row = w + rr * 16;
        const float inv = sInv[row];
        const int ch8 = (2 * lane) ^ ((row & 7) << 2);
        float4 v = *(float4*)(stage + row * 512 + ch8 * 8);
        v.x *= inv; v.y *= inv; v.z *= inv; v.w *= inv;
        __stcs((float4*)&attn[((size_t)bh * L_SEQ + qb + row) * L_SEQ + kb + 4*lane], v);
    }
}

// ---------------------------------------------------------------------------
extern "C" void kernel_launch(void* const* d_in, const int* in_sizes, int n_in,
                              void* d_out, int out_size)
{
    const float* q    = (const float*)d_in[0];
    const float* k    = (const float*)d_in[1];
    const int*   mask = (const int*)  d_in[3];
    const float* Wq   = (const float*)d_in[4];
    const float* Wk   = (const float*)d_in[5];

    float* out  = (float*)d_out;
    float* qh   = out;                                   // (2,8,2048,64)
    float* attn = out + (size_t)N_BH * L_SEQ * D_HEAD;   // (2,8,2048,2048)

    cudaFuncSetAttribute(score_f16_kernel,
                         cudaFuncAttributeMaxDynamicSharedMemorySize, 65536);

    wcvt_kernel     <<<dim3(128, 2), 256>>>(Wq, Wk);
    proj_f16_kernel <<<dim3(4, 32, 2), 256>>>(q, k, qh);
    score_f16_kernel<<<dim3(NKB2, L_SEQ / QTILE, N_BH), 512, 65536>>>(mask, attn);
}

// round 15
// speedup vs baseline: 1.0654x; 1.0654x over previous
#include <cuda_runtime.h>
#include <cuda_fp16.h>
#include <cstdint>

#define L_SEQ   2048
#define D_HEAD  64
#define N_HEADS 8
#define N_BH    16
#define D_IN    512
#define QTILE   128
#define KTILE   128
#define NKB2    (L_SEQ / KTILE)     // 16 k-chunks per row group

// Static device scratch (no allocs allowed)
__device__ __half g_q16[N_BH * L_SEQ * D_HEAD];          // 4 MB, qh/8 in fp16
__device__ __half g_k16[N_BH * L_SEQ * D_HEAD];          // 4 MB, kh in fp16
__device__ float  g_part[N_BH * L_SEQ * NKB2];           // 2 MB partial row sums
__device__ int    g_cnt[N_BH * (L_SEQ / QTILE)];         // 256 group counters

// ---------------------------------------------------------------------------
// FFMA-only 2^t, degree-4 (|rel err| ~4e-5, ample vs 3e-4 fp16-GEMM budget)
// ---------------------------------------------------------------------------
__device__ __forceinline__ float exp2_fast(float t)
{
    const float MAGIC = 12582912.0f;            // 1.5 * 2^23
    float z = t + MAGIC;
    float n = z - MAGIC;                        // rint(t)
    float f = t - n;                            // f in [-0.5, 0.5]
    float p = 0.009618129107628477f;
    p = fmaf(p, f, 0.05550410866482158f);
    p = fmaf(p, f, 0.24022650695910072f);
    p = fmaf(p, f, 0.6931471805599453f);
    p = fmaf(p, f, 1.0f);
    return __int_as_float(__float_as_int(p) + (((int)n) << 23));
}

__device__ __forceinline__ void mma_f16(float* c,
    uint32_t a0, uint32_t a1, uint32_t a2, uint32_t a3,
    uint32_t b0, uint32_t b1)
{
    asm volatile(
        "mma.sync.aligned.m16n8k16.row.col.f32.f16.f16.f32 "
        "{%0,%1,%2,%3}, {%4,%5,%6,%7}, {%8,%9}, {%0,%1,%2,%3};"
        : "+f"(c[0]), "+f"(c[1]), "+f"(c[2]), "+f"(c[3])
        : "r"(a0), "r"(a1), "r"(a2), "r"(a3), "r"(b0), "r"(b1));
}

__device__ __forceinline__ void ldsm4(uint32_t& r0, uint32_t& r1,
                                      uint32_t& r2, uint32_t& r3, uint32_t a)
{
    asm volatile("ldmatrix.sync.aligned.m8n8.x4.shared.b16 {%0,%1,%2,%3}, [%4];"
                 : "=r"(r0), "=r"(r1), "=r"(r2), "=r"(r3) : "r"(a));
}

__device__ __forceinline__ uint32_t smem_u32(const void* p) {
    uint32_t a;
    asm("{ .reg .u64 t; cvta.to.shared.u64 t, %1; cvt.u32.u64 %0, t; }" : "=r"(a) : "l"(p));
    return a;
}

// pack 8 fp32 -> 8 fp16 (hi) and 8 fp16 (lo residual)
__device__ __forceinline__ void split8(const float* x, uint4& hi, uint4& lo)
{
    __half2 h[4], l[4];
    #pragma unroll
    for (int i = 0; i < 4; i++) {
        float v0 = x[2*i], v1 = x[2*i+1];
        __half h0 = __float2half_rn(v0);
        __half h1 = __float2half_rn(v1);
        __half l0 = __float2half_rn(v0 - __half2float(h0));
        __half l1 = __float2half_rn(v1 - __half2float(h1));
        h[i] = __halves2half2(h0, h1);
        l[i] = __halves2half2(l0, l1);
    }
    hi = *(uint4*)h;
    lo = *(uint4*)l;
}

// ---------------------------------------------------------------------------
// Projection via fp16 hi/lo split (3 passes: hh + hl + lh) — fp32-accurate.
// Software-pipelined: next k-slice gmem loads issued before current compute.
// ---------------------------------------------------------------------------
#define PKS 32

__global__ __launch_bounds__(256) void proj_f16_kernel(
    const float* __restrict__ q, const float* __restrict__ k,
    const float* __restrict__ Wq, const float* __restrict__ Wk,
    float* __restrict__ qh_out)
{
    __shared__ __align__(16) char sAhi[128 * 64];
    __shared__ __align__(16) char sAlo[128 * 64];
    __shared__ __align__(16) char sBhi[128 * 64];
    __shared__ __align__(16) char sBlo[128 * 64];

    const int tid = threadIdx.x;

    if (blockIdx.x == 0 && blockIdx.y == 0 && blockIdx.z == 0 && tid < 256)
        g_cnt[tid] = 0;

    const int z = blockIdx.z;
    const float* X = z ? k  : q;
    const float* W = z ? Wk : Wq;

    const int w    = tid >> 5;
    const int lane = tid & 31;
    const int g    = lane >> 2;
    const int t    = lane & 3;
    const int wr   = w & 3;
    const int wc   = w >> 2;
    const int n0   = blockIdx.y * 128;
    const int o0   = blockIdx.x * 128;

    const uint32_t sAhiB = smem_u32(sAhi), sAloB = smem_u32(sAlo);
    const uint32_t sBhiB = smem_u32(sBhi), sBloB = smem_u32(sBlo);

    float c[2][8][4];
    #pragma unroll
    for (int mt = 0; mt < 2; mt++)
        #pragma unroll
        for (int j = 0; j < 8; j++)
            #pragma unroll
            for (int q2 = 0; q2 < 4; q2++) c[mt][j][q2] = 0.f;

    const int R0 = wr * 32;
    const int C0 = wc * 64;

    const int aHalf = lane >> 4;
    uint32_t aRow[2]; int aXor[2];
    #pragma unroll
    for (int mt = 0; mt < 2; mt++) {
        int row = R0 + mt*16 + (lane & 15);
        aRow[mt] = row * 64;
        aXor[mt] = (row >> 1) & 3;
    }
    const int qd = lane >> 3;
    const int bHalf = qd & 1;
    uint32_t bRow[4]; int bXor[4];
    #pragma unroll
    for (int jp = 0; jp < 4; jp++) {
        int row = C0 + (jp*2 + (qd >> 1)) * 8 + (lane & 7);
        bRow[jp] = row * 64;
        bXor[jp] = (row >> 1) & 3;
    }

    // loader geometry (fixed per thread)
    const int lrr[2] = { (tid + 0)   >> 2, (tid + 256) >> 2 };
    const int lch[2] = { (tid + 0) & 3,    (tid + 256) & 3 };

    // prologue: load k0 = 0
    float xv[2][8], wv[2][8];
    #pragma unroll
    for (int i = 0; i < 2; i++) {
        *(float4*)&xv[i][0] = *(const float4*)&X[(size_t)(n0 + lrr[i]) * D_IN + lch[i]*8];
        *(float4*)&xv[i][4] = *(const float4*)&X[(size_t)(n0 + lrr[i]) * D_IN + lch[i]*8 + 4];
        *(float4*)&wv[i][0] = *(const float4*)&W[(size_t)(o0 + lrr[i]) * D_IN + lch[i]*8];
        *(float4*)&wv[i][4] = *(const float4*)&W[(size_t)(o0 + lrr[i]) * D_IN + lch[i]*8 + 4];
    }

    for (int k0 = 0; k0 < D_IN; k0 += PKS) {
        __syncthreads();                       // prev compute done reading smem
        #pragma unroll
        for (int i = 0; i < 2; i++) {
            int off = lrr[i] * 64 + (lch[i] ^ ((lrr[i] >> 1) & 3)) * 16;
            uint4 hi, lo;
            split8(xv[i], hi, lo);
            *(uint4*)(sAhi + off) = hi;
            *(uint4*)(sAlo + off) = lo;
            split8(wv[i], hi, lo);
            *(uint4*)(sBhi + off) = hi;
            *(uint4*)(sBlo + off) = lo;
        }
        __syncthreads();

        // prefetch next slice while tensor pipe chews on this one
        const int kn = k0 + PKS;
        if (kn < D_IN) {
            #pragma unroll
            for (int i = 0; i < 2; i++) {
                *(float4*)&xv[i][0] = *(const float4*)&X[(size_t)(n0 + lrr[i]) * D_IN + kn + lch[i]*8];
                *(float4*)&xv[i][4] = *(const float4*)&X[(size_t)(n0 + lrr[i]) * D_IN + kn + lch[i]*8 + 4];
                *(float4*)&wv[i][0] = *(const float4*)&W[(size_t)(o0 + lrr[i]) * D_IN + kn + lch[i]*8];
                *(float4*)&wv[i][4] = *(const float4*)&W[(size_t)(o0 + lrr[i]) * D_IN + kn + lch[i]*8 + 4];
            }
        }

        #pragma unroll
        for (int s = 0; s < 2; s++) {
            uint32_t ah[2][4], al[2][4];
            #pragma unroll
            for (int mt = 0; mt < 2; mt++) {
                int chk = ((2*s + aHalf) ^ aXor[mt]) * 16;
                ldsm4(ah[mt][0], ah[mt][1], ah[mt][2], ah[mt][3], sAhiB + aRow[mt] + chk);
                ldsm4(al[mt][0], al[mt][1], al[mt][2], al[mt][3], sAloB + aRow[mt] + chk);
            }
            uint32_t bh[8][2], bl[8][2];
            #pragma unroll
            for (int jp = 0; jp < 4; jp++) {
                int chk = ((2*s + bHalf) ^ bXor[jp]) * 16;
                uint32_t r0, r1, r2, r3;
                ldsm4(r0, r1, r2, r3, sBhiB + bRow[jp] + chk);
                bh[jp*2][0] = r0; bh[jp*2][1] = r1;
                bh[jp*2+1][0] = r2; bh[jp*2+1][1] = r3;
                ldsm4(r0, r1, r2, r3, sBloB + bRow[jp] + chk);
                bl[jp*2][0] = r0; bl[jp*2][1] = r1;
                bl[jp*2+1][0] = r2; bl[jp*2+1][1] = r3;
            }
            #pragma unroll
            for (int mt = 0; mt < 2; mt++)
                #pragma unroll
                for (int j = 0; j < 8; j++) {
                    mma_f16(c[mt][j], ah[mt][0], ah[mt][1], ah[mt][2], ah[mt][3],
                            bh[j][0], bh[j][1]);
                    mma_f16(c[mt][j], ah[mt][0], ah[mt][1], ah[mt][2], ah[mt][3],
                            bl[j][0], bl[j][1]);
                    mma_f16(c[mt][j], al[mt][0], al[mt][1], al[mt][2], al[mt][3],
                            bh[j][0], bh[j][1]);
                }
        }
    }

    const int b  = n0 >> 11;
    const int l0 = n0 & 2047;
    const int h  = (o0 >> 6) + wc;
    const size_t hb = (size_t)(b * N_HEADS + h) * L_SEQ * D_HEAD;
    __half* H = z ? g_k16 : g_q16;
    const float sc = z ? 1.0f : 0.125f;
    #pragma unroll
    for (int mt = 0; mt < 2; mt++) {
        const int r0 = l0 + R0 + mt*16 + g;
        #pragma unroll
        for (int j = 0; j < 8; j++) {
            const int d = j*8 + 2*t;
            if (!z) {
                *(float2*)&qh_out[hb + (size_t)r0       * D_HEAD + d] = make_float2(c[mt][j][0], c[mt][j][1]);
                *(float2*)&qh_out[hb + (size_t)(r0 + 8) * D_HEAD + d] = make_float2(c[mt][j][2], c[mt][j][3]);
            }
            *(__half2*)&H[hb + (size_t)r0       * D_HEAD + d] =
                __floats2half2_rn(c[mt][j][0] * sc, c[mt][j][1] * sc);
            *(__half2*)&H[hb + (size_t)(r0 + 8) * D_HEAD + d] =
                __floats2half2_rn(c[mt][j][2] * sc, c[mt][j][3] * sc);
        }
    }
}

// ---------------------------------------------------------------------------
// fp16 scores, 512 threads / 16 warps (4x4), warp tile 32x32. (R12 epilogue:
// fragment-direct streaming stores — staging variant regressed.)
// ---------------------------------------------------------------------------
__global__ __launch_bounds__(512, 2) void score_f16_kernel(
    const int* __restrict__ mask, float* __restrict__ attn)
{
    __shared__ __align__(16) char sQraw[128 * 128];   // 16 KB, swizzled fp16
    __shared__ __align__(16) char sKraw[128 * 128];   // 16 KB
    __shared__ float sMaskF[KTILE];
    __shared__ float sRS[4][QTILE];
    __shared__ float sInv[QTILE];

    const int tid  = threadIdx.x;
    const int w    = tid >> 5;
    const int lane = tid & 31;
    const int g    = lane >> 2;
    const int t    = lane & 3;
    const int wr   = w & 3;            // row block (32 rows)
    const int wc   = w >> 2;           // col block (32 cols)

    const int kbi = blockIdx.x;
    const int kb  = kbi * KTILE;
    const int qb  = blockIdx.y * QTILE;
    const int bh  = blockIdx.z;
    const int gi  = bh * (L_SEQ / QTILE) + blockIdx.y;

    const uint4* Qg = (const uint4*)(g_q16 + ((size_t)bh * L_SEQ + qb) * D_HEAD);
    const uint4* Kg = (const uint4*)(g_k16 + ((size_t)bh * L_SEQ + kb) * D_HEAD);
    #pragma unroll
    for (int i = 0; i < 2; i++) {
        int idx = tid + 512 * i;               // 1024 chunks per tile
        int r = idx >> 3, ch = idx & 7;
        int chs = ch ^ (r & 7);
        *(uint4*)(sQraw + r * 128 + chs * 16) = Qg[idx];
        *(uint4*)(sKraw + r * 128 + chs * 16) = Kg[idx];
    }
    if (tid < KTILE) sMaskF[tid] = mask[(bh >> 3) * L_SEQ + kb + tid] ? 1.0f : 0.0f;
    __syncthreads();

    const uint32_t sQb = smem_u32(sQraw);
    const uint32_t sKb = smem_u32(sKraw);
    const int R0 = wr * 32;
    const int C0 = wc * 32;

    const int aHalf = lane >> 4;
    uint32_t aBase[2]; int aXor[2];
    #pragma unroll
    for (int mt = 0; mt < 2; mt++) {
        int row = R0 + mt*16 + (lane & 15);
        aBase[mt] = sQb + row * 128;
        aXor[mt]  = row & 7;
    }
    const int qd = lane >> 3;
    const int bHalf = qd & 1;
    uint32_t bBase[2]; int bXor[2];
    #pragma unroll
    for (int jp = 0; jp < 2; jp++) {
        int row = C0 + (jp*2 + (qd >> 1)) * 8 + (lane & 7);
        bBase[jp] = sKb + row * 128;
        bXor[jp]  = row & 7;
    }

    float c[2][4][4];
    #pragma unroll
    for (int mt = 0; mt < 2; mt++)
        #pragma unroll
        for (int j = 0; j < 4; j++)
            #pragma unroll
            for (int q2 = 0; q2 < 4; q2++) c[mt][j][q2] = 0.f;

    #pragma unroll
    for (int s = 0; s < 4; s++) {
        uint32_t a[2][4];
        #pragma unroll
        for (int mt = 0; mt < 2; mt++) {
            int chk = (2*s + aHalf) ^ aXor[mt];
            ldsm4(a[mt][0], a[mt][1], a[mt][2], a[mt][3], aBase[mt] + chk * 16);
        }
        uint32_t b[4][2];
        #pragma unroll
        for (int jp = 0; jp < 2; jp++) {
            int chk = (2*s + bHalf) ^ bXor[jp];
            uint32_t r0, r1, r2, r3;
            ldsm4(r0, r1, r2, r3, bBase[jp] + chk * 16);
            b[jp*2][0] = r0; b[jp*2][1] = r1;
            b[jp*2+1][0] = r2; b[jp*2+1][1] = r3;
        }
        #pragma unroll
        for (int mt = 0; mt < 2; mt++)
            #pragma unroll
            for (int j = 0; j < 4; j++)
                mma_f16(c[mt][j], a[mt][0], a[mt][1], a[mt][2], a[mt][3],
                        b[j][0], b[j][1]);
    }

    // exp (score already /8 via q16 scale) + mask; per-thread row sums
    const float C = 1.4426950408889634f;       // log2(e)
    float rs[4] = {0.f, 0.f, 0.f, 0.f};
    #pragma unroll
    for (int mt = 0; mt < 2; mt++) {
        #pragma unroll
        for (int j = 0; j < 4; j++) {
            const int col = C0 + j*8 + 2*t;
            const float m0 = sMaskF[col], m1 = sMaskF[col + 1];
            float v0 = exp2_fast(c[mt][j][0] * C) * m0;
            float v1 = exp2_fast(c[mt][j][1] * C) * m1;
            float v2 = exp2_fast(c[mt][j][2] * C) * m0;
            float v3 = exp2_fast(c[mt][j][3] * C) * m1;
            c[mt][j][0] = v0; c[mt][j][1] = v1; c[mt][j][2] = v2; c[mt][j][3] = v3;
            rs[mt*2 + 0] += v0 + v1;
            rs[mt*2 + 1] += v2 + v3;
        }
    }
    #pragma unroll
    for (int off = 1; off <= 2; off <<= 1)
        #pragma unroll
        for (int i = 0; i < 4; i++)
            rs[i] += __shfl_xor_sync(0xffffffffu, rs[i], off);
    if (t == 0) {
        sRS[wc][R0 +  0 + g] = rs[0];
        sRS[wc][R0 +  8 + g] = rs[1];
        sRS[wc][R0 + 16 + g] = rs[2];
        sRS[wc][R0 + 24 + g] = rs[3];
    }
    __syncthreads();

    if (tid < QTILE)
        g_part[((size_t)bh * L_SEQ + qb + tid) * NKB2 + kbi] =
            (sRS[0][tid] + sRS[1][tid]) + (sRS[2][tid] + sRS[3][tid]);
    __syncthreads();

    // Cross-CTA: release, count in, spin for the 16-CTA row group
    if (tid == 0) {
        __threadfence();
        atomicAdd(&g_cnt[gi], 1);
        while (atomicAdd(&g_cnt[gi], 0) < NKB2) __nanosleep(128);
        __threadfence();
    }
    __syncthreads();

    if (tid < QTILE) {
        const float4* p = (const float4*)(g_part + ((size_t)bh * L_SEQ + qb + tid) * NKB2);
        float s = 0.f;
        #pragma unroll
        for (int i = 0; i < NKB2 / 4; i++) {
            float4 v = p[i];
            s += (v.x + v.y) + (v.z + v.w);
        }
        sInv[tid] = 1.0f / s;
    }
    __syncthreads();

    // Normalized streaming writes straight from fragments
    float* Abase = attn + ((size_t)bh * L_SEQ + qb) * L_SEQ + kb;
    #pragma unroll
    for (int mt = 0; mt < 2; mt++) {
        const int r0 = R0 + mt*16 + g;
        const float i0 = sInv[r0];
        const float i1 = sInv[r0 + 8];
        #pragma unroll
        for (int j = 0; j < 4; j++) {
            const int col = C0 + j*8 + 2*t;
            float2 o0 = make_float2(c[mt][j][0] * i0, c[mt][j][1] * i0);
            float2 o1 = make_float2(c[mt][j][2] * i1, c[mt][j][3] * i1);
            __stcs((float2*)&Abase[(size_t)r0       * L_SEQ + col], o0);
            __stcs((float2*)&Abase[(size_t)(r0 + 8) * L_SEQ + col], o1);
        }
    }
}

// ---------------------------------------------------------------------------
extern "C" void kernel_launch(void* const* d_in, const int* in_sizes, int n_in,
                              void* d_out, int out_size)
{
    const float* q    = (const float*)d_in[0];
    const float* k    = (const float*)d_in[1];
    const int*   mask = (const int*)  d_in[3];
    const float* Wq   = (const float*)d_in[4];
    const float* Wk   = (const float*)d_in[5];

    float* out  = (float*)d_out;
    float* qh   = out;                                   // (2,8,2048,64)
    float* attn = out + (size_t)N_BH * L_SEQ * D_HEAD;   // (2,8,2048,2048)

    proj_f16_kernel <<<dim3(4, 32, 2), 256>>>(q, k, Wq, Wk, qh);
    score_f16_kernel<<<dim3(NKB2, L_SEQ / QTILE, N_BH), 512>>>(mask, attn);
}